// round 3
// baseline (speedup 1.0000x reference)
#include <cuda_runtime.h>
#include <cuda_bf16.h>
#include <cstdint>

// ---------------- problem constants ----------------
#define ND 40000
#define NP 20000
#define RR 4
#define E_DDI 200000
#define E_PDI 200000
#define FD 128
#define FP 256
#define FO 128

// ---------------- scratch (device globals; no allocation allowed) ----------
#define OFF_TMP    0
#define OFF_TMP_P  (RR*ND*FO)                       // 20,480,000
#define OFF_H1     (OFF_TMP_P + NP*FO)              // 23,040,000
#define OFF_H2     (OFF_H1 + ND*FO)                 // 28,160,000
#define OFF_RS     (OFF_H2 + ND*FO)                 // 33,280,000
#define RS_DOUT_DDI 0
#define RS_DIN_DDI  (RR*ND)
#define RS_DOUT_PDI (2*RR*ND)
#define RS_DIN_PDI  (2*RR*ND + NP)
#define N_RS        (2*RR*ND + NP + ND)             // 380,000
#define N_SCRATCH   (OFF_RS + N_RS)

__device__ float g_scratch[N_SCRATCH];
__device__ int   g_deg[N_RS];

// ---------------- kernels ----------------
__global__ void k_zero_i32(int* __restrict__ p, int n) {
    int i = blockIdx.x * blockDim.x + threadIdx.x;
    if (i < n) p[i] = 0;
}

// DDI degrees over all RR relations at once. src/dst laid [RR][E_DDI].
// 4 edges per thread (E_DDI divisible by 4, so quads never straddle relations).
__global__ void k_deg_ddi(const int* __restrict__ src, const int* __restrict__ dst,
                          int* __restrict__ deg) {
    int i = blockIdx.x * blockDim.x + threadIdx.x;   // quad index
    if (i >= (RR * E_DDI) / 4) return;
    int r = (i * 4) / E_DDI;
    int4 s = __ldg((const int4*)(src) + i);
    int4 d = __ldg((const int4*)(dst) + i);
    int* dout = &deg[RS_DOUT_DDI + r * ND];
    int* din  = &deg[RS_DIN_DDI  + r * ND];
    atomicAdd(&dout[s.x], 1); atomicAdd(&dout[s.y], 1);
    atomicAdd(&dout[s.z], 1); atomicAdd(&dout[s.w], 1);
    atomicAdd(&din[d.x], 1);  atomicAdd(&din[d.y], 1);
    atomicAdd(&din[d.z], 1);  atomicAdd(&din[d.w], 1);
}

__global__ void k_deg_pdi(const int* __restrict__ src, const int* __restrict__ dst,
                          int* __restrict__ deg) {
    int i = blockIdx.x * blockDim.x + threadIdx.x;
    if (i >= E_PDI / 4) return;
    int4 s = __ldg((const int4*)(src) + i);
    int4 d = __ldg((const int4*)(dst) + i);
    atomicAdd(&deg[RS_DOUT_PDI + s.x], 1); atomicAdd(&deg[RS_DOUT_PDI + s.y], 1);
    atomicAdd(&deg[RS_DOUT_PDI + s.z], 1); atomicAdd(&deg[RS_DOUT_PDI + s.w], 1);
    atomicAdd(&deg[RS_DIN_PDI + d.x], 1);  atomicAdd(&deg[RS_DIN_PDI + d.y], 1);
    atomicAdd(&deg[RS_DIN_PDI + d.z], 1);  atomicAdd(&deg[RS_DIN_PDI + d.w], 1);
}

__global__ void k_rs(const int* __restrict__ deg, float* __restrict__ rs, int n) {
    int i = blockIdx.x * blockDim.x + threadIdx.x;
    if (i < n) rs[i] = rsqrtf((float)max(deg[i], 1));
}

// h[i*FO + j] = sum_r b[r*FO + j] (+ bx[j] if bx != null)
__global__ void k_init_out(float* __restrict__ h, const float* __restrict__ b,
                           const float* __restrict__ bx, int n) {
    int i = blockIdx.x * blockDim.x + threadIdx.x;
    if (i >= n) return;
    int j = i & (FO - 1);
    float v = b[0 * FO + j] + b[1 * FO + j] + b[2 * FO + j] + b[3 * FO + j];
    if (bx) v += bx[j];
    h[i] = v;
}

// Batched normalized GEMM: out[r][m][n] = (act(X[m,:]) * rs[r][m]) @ W[r][:,:]
// X: [M,K] row-major (shared across relations), W: [Rb,K,FO], rs: [Rb,M],
// out: [Rb,M,FO].  relation r = blockIdx.z.  BM=128, BN=FO=128, BK=8, 256 thr.
template<bool RELU>
__global__ void __launch_bounds__(256)
k_gemm(const float* __restrict__ X, const float* __restrict__ W,
       const float* __restrict__ rs, float* __restrict__ out,
       int M, int K) {
    const int r = blockIdx.z;
    const int rowBase = blockIdx.x * 128;
    __shared__ float As[8][128];
    __shared__ float Bs[8][128];

    const int tid = threadIdx.x;
    const int tx = tid & 15;        // 0..15  -> col block of 8
    const int ty = tid >> 4;        // 0..15  -> row block of 8

    const float* Wr  = W  + (size_t)r * K * FO;
    const float* rsr = rs + (size_t)r * M;
    float* outr      = out + (size_t)r * M * FO;

    // A-load mapping: thread -> (row am, k-offset ak), one float4 each
    const int am = tid >> 1;          // 0..127
    const int ak = (tid & 1) * 4;     // 0 or 4
    const int grow = rowBase + am;
    const bool rowOK = (grow < M);
    const float scale = rowOK ? __ldg(&rsr[grow]) : 0.0f;
    const float* Xrow = X + (size_t)(rowOK ? grow : 0) * K + ak;

    // B-load mapping
    const int bk = tid >> 5;          // 0..7
    const int bn = (tid & 31) * 4;    // 0..124

    float acc[8][8];
#pragma unroll
    for (int i = 0; i < 8; i++)
#pragma unroll
        for (int j = 0; j < 8; j++) acc[i][j] = 0.0f;

    for (int k0 = 0; k0 < K; k0 += 8) {
        float4 av = make_float4(0.f, 0.f, 0.f, 0.f);
        if (rowOK) av = *reinterpret_cast<const float4*>(Xrow + k0);
        if (RELU) {
            av.x = fmaxf(av.x, 0.f); av.y = fmaxf(av.y, 0.f);
            av.z = fmaxf(av.z, 0.f); av.w = fmaxf(av.w, 0.f);
        }
        av.x *= scale; av.y *= scale; av.z *= scale; av.w *= scale;
        As[ak + 0][am] = av.x;
        As[ak + 1][am] = av.y;
        As[ak + 2][am] = av.z;
        As[ak + 3][am] = av.w;

        float4 bv = *reinterpret_cast<const float4*>(Wr + (size_t)(k0 + bk) * FO + bn);
        *reinterpret_cast<float4*>(&Bs[bk][bn]) = bv;

        __syncthreads();
#pragma unroll
        for (int kk = 0; kk < 8; kk++) {
            float ra[8], rb[8];
#pragma unroll
            for (int i = 0; i < 8; i++) ra[i] = As[kk][ty * 8 + i];
#pragma unroll
            for (int j = 0; j < 8; j++) rb[j] = Bs[kk][tx * 8 + j];
#pragma unroll
            for (int i = 0; i < 8; i++)
#pragma unroll
                for (int j = 0; j < 8; j++)
                    acc[i][j] = fmaf(ra[i], rb[j], acc[i][j]);
        }
        __syncthreads();
    }

#pragma unroll
    for (int i = 0; i < 8; i++) {
        int orow = rowBase + ty * 8 + i;
        if (orow < M) {
            float4 o0 = make_float4(acc[i][0], acc[i][1], acc[i][2], acc[i][3]);
            float4 o1 = make_float4(acc[i][4], acc[i][5], acc[i][6], acc[i][7]);
            float* p = outr + (size_t)orow * FO + tx * 8;
            *reinterpret_cast<float4*>(p)     = o0;
            *reinterpret_cast<float4*>(p + 4) = o1;
        }
    }
}

// One warp per edge: h[dst] += tmp[r][src] * rs_din[r][dst].
// All RR relations in one launch: blockIdx.y = relation.
__global__ void __launch_bounds__(256)
k_scatter_ddi(const float* __restrict__ tmp, const int* __restrict__ src,
              const int* __restrict__ dst, const float* __restrict__ rsd,
              float* __restrict__ h) {
    int r = blockIdx.y;
    int warp = (blockIdx.x * blockDim.x + threadIdx.x) >> 5;
    int lane = threadIdx.x & 31;
    if (warp >= E_DDI) return;
    const int*   srcr = src + (size_t)r * E_DDI;
    const int*   dstr = dst + (size_t)r * E_DDI;
    const float* tmpr = tmp + (size_t)r * ND * FO;
    const float* rsr  = rsd + (size_t)r * ND;
    int s = __ldg(&srcr[warp]);
    int d = __ldg(&dstr[warp]);
    float sc = __ldg(&rsr[d]);
    float4 v = __ldg(reinterpret_cast<const float4*>(tmpr + (size_t)s * FO) + lane);
    float* p = h + (size_t)d * FO + lane * 4;
    atomicAdd(p + 0, v.x * sc);
    atomicAdd(p + 1, v.y * sc);
    atomicAdd(p + 2, v.z * sc);
    atomicAdd(p + 3, v.w * sc);
}

__global__ void __launch_bounds__(256)
k_scatter_pdi(const float* __restrict__ tmp, const int* __restrict__ src,
              const int* __restrict__ dst, const float* __restrict__ rsd,
              float* __restrict__ h) {
    int warp = (blockIdx.x * blockDim.x + threadIdx.x) >> 5;
    int lane = threadIdx.x & 31;
    if (warp >= E_PDI) return;
    int s = __ldg(&src[warp]);
    int d = __ldg(&dst[warp]);
    float sc = __ldg(&rsd[d]);
    float4 v = __ldg(reinterpret_cast<const float4*>(tmp + (size_t)s * FO) + lane);
    float* p = h + (size_t)d * FO + lane * 4;
    atomicAdd(p + 0, v.x * sc);
    atomicAdd(p + 1, v.y * sc);
    atomicAdd(p + 2, v.z * sc);
    atomicAdd(p + 3, v.w * sc);
}

// ---------------- launch ----------------
extern "C" void kernel_launch(void* const* d_in, const int* in_sizes, int n_in,
                              void* d_out, int out_size) {
    const float* x_d    = (const float*)d_in[0];
    const float* x_p    = (const float*)d_in[1];
    const float* W1     = (const float*)d_in[2];
    const float* b1     = (const float*)d_in[3];
    const float* W1_pdi = (const float*)d_in[4];
    const float* b1_pdi = (const float*)d_in[5];
    // d_in[6], d_in[7]: W1_ppi / b1_ppi — dead code (protein branch never reaches output)
    const float* W2     = (const float*)d_in[8];
    const float* b2     = (const float*)d_in[9];
    const float* W3     = (const float*)d_in[10];
    const float* b3     = (const float*)d_in[11];
    const int* ddi_src  = (const int*)d_in[12];
    const int* ddi_dst  = (const int*)d_in[13];
    const int* pdi_src  = (const int*)d_in[14];
    const int* pdi_dst  = (const int*)d_in[15];
    // d_in[16], d_in[17]: ppi edges — unused

    float* out = (float*)d_out;

    void* sp = nullptr; void* dp = nullptr;
    cudaGetSymbolAddress(&sp, g_scratch);
    cudaGetSymbolAddress(&dp, g_deg);
    float* S   = (float*)sp;
    int*   DEG = (int*)dp;

    float* tmp   = S + OFF_TMP;
    float* tmp_p = S + OFF_TMP_P;
    float* h1    = S + OFF_H1;
    float* h2    = S + OFF_H2;
    float* RS    = S + OFF_RS;
    float* rs_dout_ddi = RS + RS_DOUT_DDI;
    float* rs_din_ddi  = RS + RS_DIN_DDI;
    float* rs_dout_pdi = RS + RS_DOUT_PDI;
    float* rs_din_pdi  = RS + RS_DIN_PDI;

    const int TPB = 256;
    const int gridM  = (ND + 127) / 128;   // 313
    const int gridMp = (NP + 127) / 128;   // 157
    const dim3 scatGrid((E_DDI + 7) / 8, RR);   // 8 edges (warps) per block
    const int scatBlkP = (E_PDI + 7) / 8;
    const int initBlk = (ND * FO + TPB - 1) / TPB;

    // ---- degrees (once; identical across layers) ----
    k_zero_i32<<<(N_RS + TPB - 1) / TPB, TPB>>>(DEG, N_RS);
    k_deg_ddi<<<(RR * E_DDI / 4 + TPB - 1) / TPB, TPB>>>(ddi_src, ddi_dst, DEG);
    k_deg_pdi<<<(E_PDI / 4 + TPB - 1) / TPB, TPB>>>(pdi_src, pdi_dst, DEG);
    k_rs<<<(N_RS + TPB - 1) / TPB, TPB>>>(DEG, RS, N_RS);

    // ---- layer 1 ----
    k_gemm<false><<<dim3(gridM, 1, RR), TPB>>>(x_d, W1, rs_dout_ddi, tmp, ND, FD);
    k_gemm<false><<<dim3(gridMp, 1, 1), TPB>>>(x_p, W1_pdi, rs_dout_pdi, tmp_p, NP, FP);
    k_init_out<<<initBlk, TPB>>>(h1, b1, b1_pdi, ND * FO);
    k_scatter_ddi<<<scatGrid, TPB>>>(tmp, ddi_src, ddi_dst, rs_din_ddi, h1);
    k_scatter_pdi<<<scatBlkP, TPB>>>(tmp_p, pdi_src, pdi_dst, rs_din_pdi, h1);
    // relu(h1) folded into next GEMM's A-load

    // ---- layer 2 ----
    k_gemm<true><<<dim3(gridM, 1, RR), TPB>>>(h1, W2, rs_dout_ddi, tmp, ND, FO);
    k_init_out<<<initBlk, TPB>>>(h2, b2, nullptr, ND * FO);
    k_scatter_ddi<<<scatGrid, TPB>>>(tmp, ddi_src, ddi_dst, rs_din_ddi, h2);

    // ---- layer 3 (no relu at the end; write straight into d_out) ----
    k_gemm<true><<<dim3(gridM, 1, RR), TPB>>>(h2, W3, rs_dout_ddi, tmp, ND, FO);
    k_init_out<<<initBlk, TPB>>>(out, b3, nullptr, ND * FO);
    k_scatter_ddi<<<scatGrid, TPB>>>(tmp, ddi_src, ddi_dst, rs_din_ddi, out);

    (void)in_sizes; (void)n_in; (void)out_size;
}

// round 5
// speedup vs baseline: 1.8357x; 1.8357x over previous
#include <cuda_runtime.h>
#include <cuda_bf16.h>
#include <cstdint>

// ---------------- problem constants ----------------
#define ND 40000
#define NP 20000
#define RR 4
#define E_DDI 200000
#define E_PDI 200000
#define FD 128
#define FP 256
#define FO 128

#define NBUCK (RR*ND + ND)            // DDI (r,d) buckets + PDI d buckets = 200000
#define NEDGE (RR*E_DDI + E_PDI)      // 1,000,000
#define NB_SCAN ((NBUCK + 1023) / 1024)   // 196

// ---------------- float scratch ----------------
#define OFF_TMP    0
#define OFF_TMP_P  (RR*ND*FO)
#define OFF_H1     (OFF_TMP_P + NP*FO)
#define OFF_H2     (OFF_H1 + ND*FO)
#define OFF_RS     (OFF_H2 + ND*FO)
// RS / DEG ordering: dout_ddi(4ND) | dout_pdi(NP) | din_ddi(4ND) | din_pdi(ND)
#define RS_DOUT_DDI 0
#define RS_DOUT_PDI (RR*ND)
#define RS_DIN      (RR*ND + NP)          // din section contiguous, length NBUCK
#define N_RS        (RR*ND + NP + NBUCK)  // 380,000
#define N_SCRATCH   (OFF_RS + N_RS)

__device__ float g_scratch[N_SCRATCH];

// ---------------- int scratch ----------------
#define IOFF_DEG    0
#define IOFF_ROWPTR (N_RS)
#define IOFF_CURSOR (IOFF_ROWPTR + NBUCK)
#define IOFF_EIDX   (IOFF_CURSOR + NBUCK)
#define IOFF_AUX    (IOFF_EIDX + NEDGE)
#define N_ISCRATCH  (IOFF_AUX + NB_SCAN + 1)

__device__ int g_iscratch[N_ISCRATCH];

// ---------------- degree / setup kernels ----------------
__global__ void k_zero_i32(int* __restrict__ p, int n) {
    int i = blockIdx.x * blockDim.x + threadIdx.x;
    if (i < n) p[i] = 0;
}

__global__ void k_deg_ddi(const int* __restrict__ src, const int* __restrict__ dst,
                          int* __restrict__ deg) {
    int i = blockIdx.x * blockDim.x + threadIdx.x;   // quad index
    if (i >= (RR * E_DDI) / 4) return;
    int r = (i * 4) / E_DDI;
    int4 s = __ldg((const int4*)(src) + i);
    int4 d = __ldg((const int4*)(dst) + i);
    int* dout = &deg[RS_DOUT_DDI + r * ND];
    int* din  = &deg[RS_DIN      + r * ND];
    atomicAdd(&dout[s.x], 1); atomicAdd(&dout[s.y], 1);
    atomicAdd(&dout[s.z], 1); atomicAdd(&dout[s.w], 1);
    atomicAdd(&din[d.x], 1);  atomicAdd(&din[d.y], 1);
    atomicAdd(&din[d.z], 1);  atomicAdd(&din[d.w], 1);
}

__global__ void k_deg_pdi(const int* __restrict__ src, const int* __restrict__ dst,
                          int* __restrict__ deg) {
    int i = blockIdx.x * blockDim.x + threadIdx.x;
    if (i >= E_PDI / 4) return;
    int4 s = __ldg((const int4*)(src) + i);
    int4 d = __ldg((const int4*)(dst) + i);
    int* dout = &deg[RS_DOUT_PDI];
    int* din  = &deg[RS_DIN + RR * ND];
    atomicAdd(&dout[s.x], 1); atomicAdd(&dout[s.y], 1);
    atomicAdd(&dout[s.z], 1); atomicAdd(&dout[s.w], 1);
    atomicAdd(&din[d.x], 1);  atomicAdd(&din[d.y], 1);
    atomicAdd(&din[d.z], 1);  atomicAdd(&din[d.w], 1);
}

__global__ void k_rs(const int* __restrict__ deg, float* __restrict__ rs, int n) {
    int i = blockIdx.x * blockDim.x + threadIdx.x;
    if (i < n) rs[i] = rsqrtf((float)max(deg[i], 1));
}

// ---------------- exclusive scan over the NBUCK din counts ----------------
__global__ void __launch_bounds__(1024)
k_scan_block(const int* __restrict__ cnt, int* __restrict__ rowptr,
             int* __restrict__ aux) {
    __shared__ int sh[1024];
    int tid = threadIdx.x;
    int i = blockIdx.x * 1024 + tid;
    int v = (i < NBUCK) ? cnt[i] : 0;
    sh[tid] = v;
    __syncthreads();
    for (int off = 1; off < 1024; off <<= 1) {
        int t = (tid >= off) ? sh[tid - off] : 0;
        __syncthreads();
        sh[tid] += t;
        __syncthreads();
    }
    if (i < NBUCK) rowptr[i] = sh[tid] - v;       // exclusive (local)
    if (tid == 1023) aux[blockIdx.x] = sh[1023];  // block total
}

__global__ void __launch_bounds__(256)
k_scan_aux(int* __restrict__ aux) {
    __shared__ int sh[256];
    int tid = threadIdx.x;
    int v = (tid < NB_SCAN) ? aux[tid] : 0;
    sh[tid] = v;
    __syncthreads();
    for (int off = 1; off < 256; off <<= 1) {
        int t = (tid >= off) ? sh[tid - off] : 0;
        __syncthreads();
        sh[tid] += t;
        __syncthreads();
    }
    if (tid < NB_SCAN) aux[tid] = sh[tid] - v;    // exclusive
}

__global__ void __launch_bounds__(1024)
k_scan_add(int* __restrict__ rowptr, int* __restrict__ cursor,
           const int* __restrict__ aux) {
    int i = blockIdx.x * 1024 + threadIdx.x;
    if (i >= NBUCK) return;
    int v = rowptr[i] + aux[blockIdx.x];
    rowptr[i] = v;
    cursor[i] = v;
}

// ---------------- edge placement (counting sort by dst bucket) -------------
__global__ void k_place_ddi(const int* __restrict__ src, const int* __restrict__ dst,
                            int* __restrict__ cursor, int* __restrict__ eidx) {
    int i = blockIdx.x * blockDim.x + threadIdx.x;
    if (i >= RR * E_DDI) return;
    int r = i / E_DDI;
    int b = r * ND + __ldg(&dst[i]);
    int pos = atomicAdd(&cursor[b], 1);
    eidx[pos] = __ldg(&src[i]);
}

__global__ void k_place_pdi(const int* __restrict__ src, const int* __restrict__ dst,
                            int* __restrict__ cursor, int* __restrict__ eidx) {
    int i = blockIdx.x * blockDim.x + threadIdx.x;
    if (i >= E_PDI) return;
    int b = RR * ND + __ldg(&dst[i]);
    int pos = atomicAdd(&cursor[b], 1);
    eidx[pos] = __ldg(&src[i]);
}

// ---------------- GEMM ----------------
// out[r][m][n] = (act(X[m,:]) * rs[r][m]) @ W[r][:,:]
// BM=128, BN=FO=128, BK=8, 256 threads, r = blockIdx.z.
template<bool RELU>
__global__ void __launch_bounds__(256)
k_gemm(const float* __restrict__ X, const float* __restrict__ W,
       const float* __restrict__ rs, float* __restrict__ out,
       int M, int K) {
    const int r = blockIdx.z;
    const int rowBase = blockIdx.x * 128;
    __shared__ float As[8][128];
    __shared__ float Bs[8][128];

    const int tid = threadIdx.x;
    const int tx = tid & 15;
    const int ty = tid >> 4;

    const float* Wr  = W  + (size_t)r * K * FO;
    const float* rsr = rs + (size_t)r * M;
    float* outr      = out + (size_t)r * M * FO;

    const int am = tid >> 1;
    const int ak = (tid & 1) * 4;
    const int grow = rowBase + am;
    const bool rowOK = (grow < M);
    const float scale = rowOK ? __ldg(&rsr[grow]) : 0.0f;
    const float* Xrow = X + (size_t)(rowOK ? grow : 0) * K + ak;

    const int bk = tid >> 5;
    const int bn = (tid & 31) * 4;

    float acc[8][8];
#pragma unroll
    for (int i = 0; i < 8; i++)
#pragma unroll
        for (int j = 0; j < 8; j++) acc[i][j] = 0.0f;

    for (int k0 = 0; k0 < K; k0 += 8) {
        float4 av = make_float4(0.f, 0.f, 0.f, 0.f);
        if (rowOK) av = *reinterpret_cast<const float4*>(Xrow + k0);
        if (RELU) {
            av.x = fmaxf(av.x, 0.f); av.y = fmaxf(av.y, 0.f);
            av.z = fmaxf(av.z, 0.f); av.w = fmaxf(av.w, 0.f);
        }
        av.x *= scale; av.y *= scale; av.z *= scale; av.w *= scale;
        As[ak + 0][am] = av.x;
        As[ak + 1][am] = av.y;
        As[ak + 2][am] = av.z;
        As[ak + 3][am] = av.w;

        float4 bv = *reinterpret_cast<const float4*>(Wr + (size_t)(k0 + bk) * FO + bn);
        *reinterpret_cast<float4*>(&Bs[bk][bn]) = bv;

        __syncthreads();
#pragma unroll
        for (int kk = 0; kk < 8; kk++) {
            float4 a0 = *reinterpret_cast<const float4*>(&As[kk][ty * 8]);
            float4 a1 = *reinterpret_cast<const float4*>(&As[kk][ty * 8 + 4]);
            float4 b0 = *reinterpret_cast<const float4*>(&Bs[kk][tx * 8]);
            float4 b1 = *reinterpret_cast<const float4*>(&Bs[kk][tx * 8 + 4]);
            float ra[8] = {a0.x, a0.y, a0.z, a0.w, a1.x, a1.y, a1.z, a1.w};
            float rb[8] = {b0.x, b0.y, b0.z, b0.w, b1.x, b1.y, b1.z, b1.w};
#pragma unroll
            for (int i = 0; i < 8; i++)
#pragma unroll
                for (int j = 0; j < 8; j++)
                    acc[i][j] = fmaf(ra[i], rb[j], acc[i][j]);
        }
        __syncthreads();
    }

#pragma unroll
    for (int i = 0; i < 8; i++) {
        int orow = rowBase + ty * 8 + i;
        if (orow < M) {
            float4 o0 = make_float4(acc[i][0], acc[i][1], acc[i][2], acc[i][3]);
            float4 o1 = make_float4(acc[i][4], acc[i][5], acc[i][6], acc[i][7]);
            float* p = outr + (size_t)orow * FO + tx * 8;
            *reinterpret_cast<float4*>(p)     = o0;
            *reinterpret_cast<float4*>(p + 4) = o1;
        }
    }
}

// ---------------- CSR gather ----------------
// h[d] = sum_r rs_din[r][d] * sum_{e in bucket(r,d)} tmp[r][src_e]  + bias
// One warp per destination row; 4 in-flight edge loads per iteration; no atomics.
__device__ __forceinline__ void acc4(float4& p, const float4 v) {
    p.x += v.x; p.y += v.y; p.z += v.z; p.w += v.w;
}

__device__ __forceinline__ float4 bucket_sum(const float* __restrict__ base,
                                             const int* __restrict__ eidx,
                                             int e, int end, int lane) {
    float4 p = make_float4(0.f, 0.f, 0.f, 0.f);
    for (; e + 3 < end; e += 4) {
        int s0 = __ldg(&eidx[e]);
        int s1 = __ldg(&eidx[e + 1]);
        int s2 = __ldg(&eidx[e + 2]);
        int s3 = __ldg(&eidx[e + 3]);
        float4 v0 = __ldg((const float4*)(base + (size_t)s0 * FO) + lane);
        float4 v1 = __ldg((const float4*)(base + (size_t)s1 * FO) + lane);
        float4 v2 = __ldg((const float4*)(base + (size_t)s2 * FO) + lane);
        float4 v3 = __ldg((const float4*)(base + (size_t)s3 * FO) + lane);
        acc4(p, v0); acc4(p, v1); acc4(p, v2); acc4(p, v3);
    }
    for (; e < end; e++) {
        int s0 = __ldg(&eidx[e]);
        acc4(p, __ldg((const float4*)(base + (size_t)s0 * FO) + lane));
    }
    return p;
}

template<bool L1>
__global__ void __launch_bounds__(256)
k_gather(const float* __restrict__ tmp, const float* __restrict__ tmp_p,
         const int* __restrict__ rowptr, const int* __restrict__ rowend,
         const int* __restrict__ eidx, const float* __restrict__ rs_din,
         const float* __restrict__ b, const float* __restrict__ b_pdi,
         float* __restrict__ h) {
    int d = (blockIdx.x * blockDim.x + threadIdx.x) >> 5;
    int lane = threadIdx.x & 31;
    if (d >= ND) return;

    float4 acc;
    {
        float4 v0 = __ldg((const float4*)(b + 0 * FO) + lane);
        float4 v1 = __ldg((const float4*)(b + 1 * FO) + lane);
        float4 v2 = __ldg((const float4*)(b + 2 * FO) + lane);
        float4 v3 = __ldg((const float4*)(b + 3 * FO) + lane);
        acc.x = v0.x + v1.x + v2.x + v3.x;
        acc.y = v0.y + v1.y + v2.y + v3.y;
        acc.z = v0.z + v1.z + v2.z + v3.z;
        acc.w = v0.w + v1.w + v2.w + v3.w;
        if (L1) {
            float4 vp = __ldg((const float4*)(b_pdi) + lane);
            acc.x += vp.x; acc.y += vp.y; acc.z += vp.z; acc.w += vp.w;
        }
    }

#pragma unroll
    for (int r = 0; r < RR; r++) {
        int bkt = r * ND + d;
        float4 p = bucket_sum(tmp + (size_t)r * ND * FO, eidx,
                              __ldg(&rowptr[bkt]), __ldg(&rowend[bkt]), lane);
        float sc = __ldg(&rs_din[bkt]);
        acc.x = fmaf(p.x, sc, acc.x); acc.y = fmaf(p.y, sc, acc.y);
        acc.z = fmaf(p.z, sc, acc.z); acc.w = fmaf(p.w, sc, acc.w);
    }

    if (L1) {
        int bkt = RR * ND + d;
        float4 p = bucket_sum(tmp_p, eidx,
                              __ldg(&rowptr[bkt]), __ldg(&rowend[bkt]), lane);
        float sc = __ldg(&rs_din[bkt]);
        acc.x = fmaf(p.x, sc, acc.x); acc.y = fmaf(p.y, sc, acc.y);
        acc.z = fmaf(p.z, sc, acc.z); acc.w = fmaf(p.w, sc, acc.w);
    }

    *((float4*)(h + (size_t)d * FO) + lane) = acc;
}

// ---------------- launch ----------------
extern "C" void kernel_launch(void* const* d_in, const int* in_sizes, int n_in,
                              void* d_out, int out_size) {
    const float* x_d    = (const float*)d_in[0];
    const float* x_p    = (const float*)d_in[1];
    const float* W1     = (const float*)d_in[2];
    const float* b1     = (const float*)d_in[3];
    const float* W1_pdi = (const float*)d_in[4];
    const float* b1_pdi = (const float*)d_in[5];
    // d_in[6], d_in[7]: W1_ppi / b1_ppi — dead code
    const float* W2     = (const float*)d_in[8];
    const float* b2     = (const float*)d_in[9];
    const float* W3     = (const float*)d_in[10];
    const float* b3     = (const float*)d_in[11];
    const int* ddi_src  = (const int*)d_in[12];
    const int* ddi_dst  = (const int*)d_in[13];
    const int* pdi_src  = (const int*)d_in[14];
    const int* pdi_dst  = (const int*)d_in[15];
    // d_in[16], d_in[17]: ppi edges — unused

    float* out = (float*)d_out;

    void* sp = nullptr; void* ip = nullptr;
    cudaGetSymbolAddress(&sp, g_scratch);
    cudaGetSymbolAddress(&ip, g_iscratch);
    float* S  = (float*)sp;
    int*   IS = (int*)ip;

    float* tmp   = S + OFF_TMP;
    float* tmp_p = S + OFF_TMP_P;
    float* h1    = S + OFF_H1;
    float* h2    = S + OFF_H2;
    float* RS    = S + OFF_RS;
    float* rs_dout_ddi = RS + RS_DOUT_DDI;
    float* rs_dout_pdi = RS + RS_DOUT_PDI;
    float* rs_din      = RS + RS_DIN;

    int* DEG    = IS + IOFF_DEG;
    int* ROWPTR = IS + IOFF_ROWPTR;
    int* CURSOR = IS + IOFF_CURSOR;
    int* EIDX   = IS + IOFF_EIDX;
    int* AUX    = IS + IOFF_AUX;

    const int TPB = 256;
    const int gridM  = (ND + 127) / 128;    // 313
    const int gridMp = (NP + 127) / 128;    // 157
    const int gatherBlk = (ND * 32 + TPB - 1) / TPB;  // warp per dst row

    // ---- degrees + CSR build (once; edges identical across layers) ----
    k_zero_i32<<<(N_RS + TPB - 1) / TPB, TPB>>>(DEG, N_RS);
    k_deg_ddi<<<(RR * E_DDI / 4 + TPB - 1) / TPB, TPB>>>(ddi_src, ddi_dst, DEG);
    k_deg_pdi<<<(E_PDI / 4 + TPB - 1) / TPB, TPB>>>(pdi_src, pdi_dst, DEG);
    k_rs<<<(N_RS + TPB - 1) / TPB, TPB>>>(DEG, RS, N_RS);
    k_scan_block<<<NB_SCAN, 1024>>>(DEG + RS_DIN, ROWPTR, AUX);
    k_scan_aux<<<1, 256>>>(AUX);
    k_scan_add<<<NB_SCAN, 1024>>>(ROWPTR, CURSOR, AUX);
    k_place_ddi<<<(RR * E_DDI + TPB - 1) / TPB, TPB>>>(ddi_src, ddi_dst, CURSOR, EIDX);
    k_place_pdi<<<(E_PDI + TPB - 1) / TPB, TPB>>>(pdi_src, pdi_dst, CURSOR, EIDX);
    // post-placement, CURSOR[b] == end of bucket b

    // ---- layer 1 ----
    k_gemm<false><<<dim3(gridM, 1, RR), TPB>>>(x_d, W1, rs_dout_ddi, tmp, ND, FD);
    k_gemm<false><<<dim3(gridMp, 1, 1), TPB>>>(x_p, W1_pdi, rs_dout_pdi, tmp_p, NP, FP);
    k_gather<true><<<gatherBlk, TPB>>>(tmp, tmp_p, ROWPTR, CURSOR, EIDX, rs_din,
                                       b1, b1_pdi, h1);
    // relu(h1) folded into next GEMM's A-load

    // ---- layer 2 ----
    k_gemm<true><<<dim3(gridM, 1, RR), TPB>>>(h1, W2, rs_dout_ddi, tmp, ND, FO);
    k_gather<false><<<gatherBlk, TPB>>>(tmp, nullptr, ROWPTR, CURSOR, EIDX, rs_din,
                                        b2, nullptr, h2);

    // ---- layer 3 ----
    k_gemm<true><<<dim3(gridM, 1, RR), TPB>>>(h2, W3, rs_dout_ddi, tmp, ND, FO);
    k_gather<false><<<gatherBlk, TPB>>>(tmp, nullptr, ROWPTR, CURSOR, EIDX, rs_din,
                                        b3, nullptr, out);

    (void)in_sizes; (void)n_in; (void)out_size;
}

// round 7
// speedup vs baseline: 2.0789x; 1.1325x over previous
#include <cuda_runtime.h>
#include <cuda_bf16.h>
#include <cstdint>

// ---------------- problem constants ----------------
#define ND 40000
#define NP 20000
#define RR 4
#define E_DDI 200000
#define E_PDI 200000
#define FD 128
#define FP 256
#define FO 128

#define NBUCK (RR*ND + ND)
#define NEDGE (RR*E_DDI + E_PDI)
#define NB_SCAN ((NBUCK + 1023) / 1024)

// ---------------- float scratch ----------------
#define OFF_TMP    0
#define OFF_TMP_P  (RR*ND*FO)
#define OFF_H1     (OFF_TMP_P + NP*FO)
#define OFF_H2     (OFF_H1 + ND*FO)
#define OFF_RS     (OFF_H2 + ND*FO)
// DEG/RS ordering: dout_ddi(4ND) | dout_pdi(NP) | din(NBUCK, contiguous)
#define RS_DOUT_DDI 0
#define RS_DOUT_PDI (RR*ND)
#define RS_DIN      (RR*ND + NP)
#define N_RS        (RR*ND + NP + NBUCK)
#define N_SCRATCH   (OFF_RS + N_RS)

__device__ float g_scratch[N_SCRATCH];

// ---------------- int scratch ----------------
#define IOFF_DEG    0
#define IOFF_ROWPTR (N_RS)
#define IOFF_CURSOR (IOFF_ROWPTR + NBUCK)
#define IOFF_EIDX   (IOFF_CURSOR + NBUCK)
#define IOFF_AUX    (IOFF_EIDX + NEDGE)
#define N_ISCRATCH  (IOFF_AUX + NB_SCAN + 1)

__device__ int g_iscratch[N_ISCRATCH];

// ---------------- degree / setup kernels (R5-proven) ----------------
__global__ void k_zero_i32(int* __restrict__ p, int n) {
    int i = blockIdx.x * blockDim.x + threadIdx.x;
    if (i < n) p[i] = 0;
}

__global__ void k_deg_ddi(const int* __restrict__ src, const int* __restrict__ dst,
                          int* __restrict__ deg) {
    int i = blockIdx.x * blockDim.x + threadIdx.x;
    if (i >= (RR * E_DDI) / 4) return;
    int r = (i * 4) / E_DDI;
    int4 s = __ldg((const int4*)(src) + i);
    int4 d = __ldg((const int4*)(dst) + i);
    int* dout = &deg[RS_DOUT_DDI + r * ND];
    int* din  = &deg[RS_DIN      + r * ND];
    atomicAdd(&dout[s.x], 1); atomicAdd(&dout[s.y], 1);
    atomicAdd(&dout[s.z], 1); atomicAdd(&dout[s.w], 1);
    atomicAdd(&din[d.x], 1);  atomicAdd(&din[d.y], 1);
    atomicAdd(&din[d.z], 1);  atomicAdd(&din[d.w], 1);
}

__global__ void k_deg_pdi(const int* __restrict__ src, const int* __restrict__ dst,
                          int* __restrict__ deg) {
    int i = blockIdx.x * blockDim.x + threadIdx.x;
    if (i >= E_PDI / 4) return;
    int4 s = __ldg((const int4*)(src) + i);
    int4 d = __ldg((const int4*)(dst) + i);
    int* dout = &deg[RS_DOUT_PDI];
    int* din  = &deg[RS_DIN + RR * ND];
    atomicAdd(&dout[s.x], 1); atomicAdd(&dout[s.y], 1);
    atomicAdd(&dout[s.z], 1); atomicAdd(&dout[s.w], 1);
    atomicAdd(&din[d.x], 1);  atomicAdd(&din[d.y], 1);
    atomicAdd(&din[d.z], 1);  atomicAdd(&din[d.w], 1);
}

__global__ void k_rs(const int* __restrict__ deg, float* __restrict__ rs, int n) {
    int i = blockIdx.x * blockDim.x + threadIdx.x;
    if (i < n) rs[i] = rsqrtf((float)max(deg[i], 1));
}

__global__ void __launch_bounds__(1024)
k_scan_block(const int* __restrict__ cnt, int* __restrict__ rowptr,
             int* __restrict__ aux) {
    __shared__ int sh[1024];
    int tid = threadIdx.x;
    int i = blockIdx.x * 1024 + tid;
    int v = (i < NBUCK) ? cnt[i] : 0;
    sh[tid] = v;
    __syncthreads();
    for (int off = 1; off < 1024; off <<= 1) {
        int t = (tid >= off) ? sh[tid - off] : 0;
        __syncthreads();
        sh[tid] += t;
        __syncthreads();
    }
    if (i < NBUCK) rowptr[i] = sh[tid] - v;
    if (tid == 1023) aux[blockIdx.x] = sh[1023];
}

__global__ void __launch_bounds__(256)
k_scan_aux(int* __restrict__ aux) {
    __shared__ int sh[256];
    int tid = threadIdx.x;
    int v = (tid < NB_SCAN) ? aux[tid] : 0;
    sh[tid] = v;
    __syncthreads();
    for (int off = 1; off < 256; off <<= 1) {
        int t = (tid >= off) ? sh[tid - off] : 0;
        __syncthreads();
        sh[tid] += t;
        __syncthreads();
    }
    if (tid < NB_SCAN) aux[tid] = sh[tid] - v;
}

__global__ void __launch_bounds__(1024)
k_scan_add(int* __restrict__ rowptr, int* __restrict__ cursor,
           const int* __restrict__ aux) {
    int i = blockIdx.x * 1024 + threadIdx.x;
    if (i >= NBUCK) return;
    int v = rowptr[i] + aux[blockIdx.x];
    rowptr[i] = v;
    cursor[i] = v;
}

__global__ void k_place_ddi(const int* __restrict__ src, const int* __restrict__ dst,
                            int* __restrict__ cursor, int* __restrict__ eidx) {
    int i = blockIdx.x * blockDim.x + threadIdx.x;
    if (i >= RR * E_DDI) return;
    int r = i / E_DDI;
    int b = r * ND + __ldg(&dst[i]);
    int pos = atomicAdd(&cursor[b], 1);
    eidx[pos] = __ldg(&src[i]);
}

__global__ void k_place_pdi(const int* __restrict__ src, const int* __restrict__ dst,
                            int* __restrict__ cursor, int* __restrict__ eidx) {
    int i = blockIdx.x * blockDim.x + threadIdx.x;
    if (i >= E_PDI) return;
    int b = RR * ND + __ldg(&dst[i]);
    int pos = atomicAdd(&cursor[b], 1);
    eidx[pos] = __ldg(&src[i]);
}

// ================= tensor-core GEMM via mma.sync (compute_100-safe) ========
// out[r][m][0:128] = (act(X[m,:]) * rs[r][m]) @ W[r][:,0:128]
// bf16 hi/lo split: aH*bH + aH*bL + aL*bH, fp32 register accumulation.
// Block 128x128, K chunked by 64. 8 warps: warp_m = wid&1 (64 rows),
// warp_n = wid>>1 (32 cols). Warp tile 64x32 = 4 m16-tiles x 4 n8-tiles.
//
// SMEM tiles are [128 rows][64 bf16] with SW128 swizzle (128B rows, 1024B
// per 8-row group). A rows = m (row-major m x k); B rows = n, cols = k —
// which IS the col-major k x n operand mma .row.col expects.
//
// ldmatrix fragment mapping (verified against PTX fragment spec):
//  A x4: lanes 0-7 -> rows m0-7 @k0, 8-15 -> m8-15 @k0, 16-23 -> m0-7 @k8,
//        24-31 -> m8-15 @k8   => regs r0..r3 = a0..a3.
//  B x4 (two n8 tiles): lanes 0-7 -> n0-7 @k0, 8-15 -> n0-7 @k8,
//        16-23 -> n8-15 @k0, 24-31 -> n8-15 @k8
//        => r0,r1 = {b0,b1} of tile q*2; r2,r3 = {b0,b1} of tile q*2+1.

__device__ __forceinline__ uint32_t smem_u32(const void* p) {
    uint32_t a;
    asm("{ .reg .u64 t; cvta.to.shared.u64 t, %1; cvt.u32.u64 %0, t; }" : "=r"(a) : "l"(p));
    return a;
}

// SW128 swizzled byte offset within a [rows x 64] bf16 tile (128B rows)
__device__ __forceinline__ uint32_t swz_off(int row, int k) {
    uint32_t b = (uint32_t)(row >> 3) * 1024u + (uint32_t)(row & 7) * 128u + (uint32_t)k * 2u;
    return b ^ ((b >> 3) & 0x70);
}

__device__ __forceinline__ void ldsm_x4(uint32_t& r0, uint32_t& r1,
                                        uint32_t& r2, uint32_t& r3, uint32_t addr) {
    asm volatile("ldmatrix.sync.aligned.m8n8.x4.shared.b16 {%0,%1,%2,%3}, [%4];"
                 : "=r"(r0), "=r"(r1), "=r"(r2), "=r"(r3) : "r"(addr));
}

__device__ __forceinline__ void mma16816(float* d, const uint32_t* a,
                                         const uint32_t* b) {
    asm volatile(
        "mma.sync.aligned.m16n8k16.row.col.f32.bf16.bf16.f32 "
        "{%0,%1,%2,%3}, {%4,%5,%6,%7}, {%8,%9}, {%0,%1,%2,%3};"
        : "+f"(d[0]), "+f"(d[1]), "+f"(d[2]), "+f"(d[3])
        : "r"(a[0]), "r"(a[1]), "r"(a[2]), "r"(a[3]), "r"(b[0]), "r"(b[1]));
}

// dynamic SMEM layout: 4 tiles x 16KB
#define GS_A_HI 0
#define GS_A_LO 16384
#define GS_B_HI 32768
#define GS_B_LO 49152
#define GS_TOTAL 65536

template<bool RELU>
__global__ void __launch_bounds__(256)
k_gemm_mma(const float* __restrict__ X, const float* __restrict__ W,
           const float* __restrict__ rs, float* __restrict__ out,
           int M, int K) {
    extern __shared__ char smem[];
    const uint32_t sb = smem_u32(smem);
    const int tid = threadIdx.x;
    const int wid = tid >> 5;
    const int lane = tid & 31;
    const int r = blockIdx.z;
    const int rowBase = blockIdx.x * 128;

    const float* Wr  = W  + (size_t)r * K * FO;
    const float* rsr = rs + (size_t)r * M;
    float* outr      = out + (size_t)r * M * FO;

    // A conversion mapping: row am = tid>>1, 32-col half = tid&1
    const int am   = tid >> 1;
    const int half = tid & 1;
    const int grow = rowBase + am;
    const bool rowOK = (grow < M);
    const float scale = rowOK ? __ldg(&rsr[grow]) : 0.0f;
    const float* Xrow = X + (size_t)(rowOK ? grow : 0) * K;

    // warp tile position
    const int wm = (wid & 1) * 64;
    const int wn = (wid >> 1) * 32;

    float acc[4][4][4];
#pragma unroll
    for (int mt = 0; mt < 4; mt++)
#pragma unroll
        for (int nt = 0; nt < 4; nt++)
#pragma unroll
            for (int q = 0; q < 4; q++) acc[mt][nt][q] = 0.0f;

    // ldmatrix per-lane source coordinates (element units)
    const int a_r = (lane & 15);             // row within m16 tile
    const int a_k = (lane >> 4) * 8;         // 0 or 8
    const int b_r = (lane & 7) + ((lane >> 4) * 8);  // row within n16 pair
    const int b_k = (lane & 8);              // 0 or 8

    const int kChunks = K >> 6;
    for (int kc = 0; kc < kChunks; kc++) {
        if (kc) __syncthreads();   // protect SMEM reuse across chunks
        // ---- convert A chunk [128 x 64] fp32 -> bf16 hi/lo, swizzled ----
        {
            const float4* src4 = (const float4*)(Xrow + kc * 64 + half * 32);
#pragma unroll
            for (int j = 0; j < 8; j++) {
                float4 v = __ldg(src4 + j);
                if (RELU) {
                    v.x = fmaxf(v.x, 0.f); v.y = fmaxf(v.y, 0.f);
                    v.z = fmaxf(v.z, 0.f); v.w = fmaxf(v.w, 0.f);
                }
                v.x *= scale; v.y *= scale; v.z *= scale; v.w *= scale;
                float vv[4] = {v.x, v.y, v.z, v.w};
                int kl = half * 32 + j * 4;
#pragma unroll
                for (int p = 0; p < 2; p++) {
                    float f0 = vv[p * 2], f1 = vv[p * 2 + 1];
                    __nv_bfloat16 h0 = __float2bfloat16(f0);
                    __nv_bfloat16 h1 = __float2bfloat16(f1);
                    __nv_bfloat16 l0 = __float2bfloat16(f0 - __bfloat162float(h0));
                    __nv_bfloat16 l1 = __float2bfloat16(f1 - __bfloat162float(h1));
                    uint32_t off = swz_off(am, kl + p * 2);
                    __nv_bfloat162 hh; hh.x = h0; hh.y = h1;
                    __nv_bfloat162 ll; ll.x = l0; ll.y = l1;
                    *(__nv_bfloat162*)(smem + GS_A_HI + off) = hh;
                    *(__nv_bfloat162*)(smem + GS_A_LO + off) = ll;
                }
            }
        }
        // ---- convert B chunk = W^T [128 n x 64 k]: B[n][k] = W[kc*64+k][n] ----
        {
#pragma unroll 4
            for (int i = 0; i < 32; i++) {
                int idx = tid + 256 * i;
                int n = idx & 127;
                int k = idx >> 7;
                float f = __ldg(&Wr[(size_t)(kc * 64 + k) * FO + n]);
                __nv_bfloat16 h = __float2bfloat16(f);
                __nv_bfloat16 l = __float2bfloat16(f - __bfloat162float(h));
                uint32_t off = swz_off(n, k);
                *(__nv_bfloat16*)(smem + GS_B_HI + off) = h;
                *(__nv_bfloat16*)(smem + GS_B_LO + off) = l;
            }
        }
        __syncthreads();

        // ---- MMA over 4 k16 steps x 3 split passes ----
#pragma unroll
        for (int ks = 0; ks < 4; ks++) {
            uint32_t aH[4][4], aL[4][4], bH[2][4], bL[2][4];
#pragma unroll
            for (int mt = 0; mt < 4; mt++) {
                uint32_t offA = swz_off(wm + mt * 16 + a_r, ks * 16 + a_k);
                ldsm_x4(aH[mt][0], aH[mt][1], aH[mt][2], aH[mt][3], sb + GS_A_HI + offA);
                ldsm_x4(aL[mt][0], aL[mt][1], aL[mt][2], aL[mt][3], sb + GS_A_LO + offA);
            }
#pragma unroll
            for (int q = 0; q < 2; q++) {
                uint32_t offB = swz_off(wn + q * 16 + b_r, ks * 16 + b_k);
                ldsm_x4(bH[q][0], bH[q][1], bH[q][2], bH[q][3], sb + GS_B_HI + offB);
                ldsm_x4(bL[q][0], bL[q][1], bL[q][2], bL[q][3], sb + GS_B_LO + offB);
            }
#pragma unroll
            for (int mt = 0; mt < 4; mt++) {
#pragma unroll
                for (int nt = 0; nt < 4; nt++) {
                    const uint32_t* bh = &bH[nt >> 1][(nt & 1) * 2];
                    const uint32_t* bl = &bL[nt >> 1][(nt & 1) * 2];
                    mma16816(acc[mt][nt], aH[mt], bh);   // hi*hi
                    mma16816(acc[mt][nt], aH[mt], bl);   // hi*lo
                    mma16816(acc[mt][nt], aL[mt], bh);   // lo*hi
                }
            }
        }
    }

    // ---- epilogue: write 64x32 warp tile to global ----
    const int erow = lane >> 2;          // 0..7
    const int ecol = (lane & 3) * 2;     // 0,2,4,6
#pragma unroll
    for (int mt = 0; mt < 4; mt++) {
#pragma unroll
        for (int nt = 0; nt < 4; nt++) {
            int row0 = rowBase + wm + mt * 16 + erow;
            int col  = wn + nt * 8 + ecol;
            if (row0 < M) {
                float2 v0 = make_float2(acc[mt][nt][0], acc[mt][nt][1]);
                *reinterpret_cast<float2*>(outr + (size_t)row0 * FO + col) = v0;
            }
            if (row0 + 8 < M) {
                float2 v1 = make_float2(acc[mt][nt][2], acc[mt][nt][3]);
                *reinterpret_cast<float2*>(outr + (size_t)(row0 + 8) * FO + col) = v1;
            }
        }
    }
}

// ---------------- CSR gather (R5-proven) ----------------
__device__ __forceinline__ void acc4(float4& p, const float4 v) {
    p.x += v.x; p.y += v.y; p.z += v.z; p.w += v.w;
}

__device__ __forceinline__ float4 bucket_sum(const float* __restrict__ base,
                                             const int* __restrict__ eidx,
                                             int e, int end, int lane) {
    float4 p = make_float4(0.f, 0.f, 0.f, 0.f);
    for (; e + 3 < end; e += 4) {
        int s0 = __ldg(&eidx[e]);
        int s1 = __ldg(&eidx[e + 1]);
        int s2 = __ldg(&eidx[e + 2]);
        int s3 = __ldg(&eidx[e + 3]);
        float4 v0 = __ldg((const float4*)(base + (size_t)s0 * FO) + lane);
        float4 v1 = __ldg((const float4*)(base + (size_t)s1 * FO) + lane);
        float4 v2 = __ldg((const float4*)(base + (size_t)s2 * FO) + lane);
        float4 v3 = __ldg((const float4*)(base + (size_t)s3 * FO) + lane);
        acc4(p, v0); acc4(p, v1); acc4(p, v2); acc4(p, v3);
    }
    for (; e < end; e++) {
        int s0 = __ldg(&eidx[e]);
        acc4(p, __ldg((const float4*)(base + (size_t)s0 * FO) + lane));
    }
    return p;
}

template<bool L1>
__global__ void __launch_bounds__(256)
k_gather(const float* __restrict__ tmp, const float* __restrict__ tmp_p,
         const int* __restrict__ rowptr, const int* __restrict__ rowend,
         const int* __restrict__ eidx, const float* __restrict__ rs_din,
         const float* __restrict__ b, const float* __restrict__ b_pdi,
         float* __restrict__ h) {
    int d = (blockIdx.x * blockDim.x + threadIdx.x) >> 5;
    int lane = threadIdx.x & 31;
    if (d >= ND) return;

    float4 acc;
    {
        float4 v0 = __ldg((const float4*)(b + 0 * FO) + lane);
        float4 v1 = __ldg((const float4*)(b + 1 * FO) + lane);
        float4 v2 = __ldg((const float4*)(b + 2 * FO) + lane);
        float4 v3 = __ldg((const float4*)(b + 3 * FO) + lane);
        acc.x = v0.x + v1.x + v2.x + v3.x;
        acc.y = v0.y + v1.y + v2.y + v3.y;
        acc.z = v0.z + v1.z + v2.z + v3.z;
        acc.w = v0.w + v1.w + v2.w + v3.w;
        if (L1) {
            float4 vp = __ldg((const float4*)(b_pdi) + lane);
            acc.x += vp.x; acc.y += vp.y; acc.z += vp.z; acc.w += vp.w;
        }
    }

#pragma unroll
    for (int r = 0; r < RR; r++) {
        int bkt = r * ND + d;
        float4 p = bucket_sum(tmp + (size_t)r * ND * FO, eidx,
                              __ldg(&rowptr[bkt]), __ldg(&rowend[bkt]), lane);
        float sc = __ldg(&rs_din[bkt]);
        acc.x = fmaf(p.x, sc, acc.x); acc.y = fmaf(p.y, sc, acc.y);
        acc.z = fmaf(p.z, sc, acc.z); acc.w = fmaf(p.w, sc, acc.w);
    }

    if (L1) {
        int bkt = RR * ND + d;
        float4 p = bucket_sum(tmp_p, eidx,
                              __ldg(&rowptr[bkt]), __ldg(&rowend[bkt]), lane);
        float sc = __ldg(&rs_din[bkt]);
        acc.x = fmaf(p.x, sc, acc.x); acc.y = fmaf(p.y, sc, acc.y);
        acc.z = fmaf(p.z, sc, acc.z); acc.w = fmaf(p.w, sc, acc.w);
    }

    *((float4*)(h + (size_t)d * FO) + lane) = acc;
}

// ---------------- launch ----------------
extern "C" void kernel_launch(void* const* d_in, const int* in_sizes, int n_in,
                              void* d_out, int out_size) {
    const float* x_d    = (const float*)d_in[0];
    const float* x_p    = (const float*)d_in[1];
    const float* W1     = (const float*)d_in[2];
    const float* b1     = (const float*)d_in[3];
    const float* W1_pdi = (const float*)d_in[4];
    const float* b1_pdi = (const float*)d_in[5];
    // d_in[6], d_in[7]: W1_ppi / b1_ppi — dead code
    const float* W2     = (const float*)d_in[8];
    const float* b2     = (const float*)d_in[9];
    const float* W3     = (const float*)d_in[10];
    const float* b3     = (const float*)d_in[11];
    const int* ddi_src  = (const int*)d_in[12];
    const int* ddi_dst  = (const int*)d_in[13];
    const int* pdi_src  = (const int*)d_in[14];
    const int* pdi_dst  = (const int*)d_in[15];
    // d_in[16], d_in[17]: ppi edges — unused

    float* out = (float*)d_out;

    void* sp = nullptr; void* ip = nullptr;
    cudaGetSymbolAddress(&sp, g_scratch);
    cudaGetSymbolAddress(&ip, g_iscratch);
    float* S  = (float*)sp;
    int*   IS = (int*)ip;

    float* tmp   = S + OFF_TMP;
    float* tmp_p = S + OFF_TMP_P;
    float* h1    = S + OFF_H1;
    float* h2    = S + OFF_H2;
    float* RS    = S + OFF_RS;
    float* rs_dout_ddi = RS + RS_DOUT_DDI;
    float* rs_dout_pdi = RS + RS_DOUT_PDI;
    float* rs_din      = RS + RS_DIN;

    int* DEG    = IS + IOFF_DEG;
    int* ROWPTR = IS + IOFF_ROWPTR;
    int* CURSOR = IS + IOFF_CURSOR;
    int* EIDX   = IS + IOFF_EIDX;
    int* AUX    = IS + IOFF_AUX;

    const int TPB = 256;
    const int gridM  = (ND + 127) / 128;    // 313
    const int gridMp = (NP + 127) / 128;    // 157
    const int gatherBlk = (ND * 32 + TPB - 1) / TPB;

    cudaFuncSetAttribute(k_gemm_mma<false>, cudaFuncAttributeMaxDynamicSharedMemorySize, GS_TOTAL);
    cudaFuncSetAttribute(k_gemm_mma<true>,  cudaFuncAttributeMaxDynamicSharedMemorySize, GS_TOTAL);

    // ---- degrees + CSR build (once; edges identical across layers) ----
    k_zero_i32<<<(N_RS + TPB - 1) / TPB, TPB>>>(DEG, N_RS);
    k_deg_ddi<<<(RR * E_DDI / 4 + TPB - 1) / TPB, TPB>>>(ddi_src, ddi_dst, DEG);
    k_deg_pdi<<<(E_PDI / 4 + TPB - 1) / TPB, TPB>>>(pdi_src, pdi_dst, DEG);
    k_rs<<<(N_RS + TPB - 1) / TPB, TPB>>>(DEG, RS, N_RS);
    k_scan_block<<<NB_SCAN, 1024>>>(DEG + RS_DIN, ROWPTR, AUX);
    k_scan_aux<<<1, 256>>>(AUX);
    k_scan_add<<<NB_SCAN, 1024>>>(ROWPTR, CURSOR, AUX);
    k_place_ddi<<<(RR * E_DDI + TPB - 1) / TPB, TPB>>>(ddi_src, ddi_dst, CURSOR, EIDX);
    k_place_pdi<<<(E_PDI + TPB - 1) / TPB, TPB>>>(pdi_src, pdi_dst, CURSOR, EIDX);

    // ---- layer 1 ----
    k_gemm_mma<false><<<dim3(gridM, 1, RR), TPB, GS_TOTAL>>>(x_d, W1, rs_dout_ddi, tmp, ND, FD);
    k_gemm_mma<false><<<dim3(gridMp, 1, 1), TPB, GS_TOTAL>>>(x_p, W1_pdi, rs_dout_pdi, tmp_p, NP, FP);
    k_gather<true><<<gatherBlk, TPB>>>(tmp, tmp_p, ROWPTR, CURSOR, EIDX, rs_din,
                                       b1, b1_pdi, h1);

    // ---- layer 2 (relu folded into A conversion) ----
    k_gemm_mma<true><<<dim3(gridM, 1, RR), TPB, GS_TOTAL>>>(h1, W2, rs_dout_ddi, tmp, ND, FO);
    k_gather<false><<<gatherBlk, TPB>>>(tmp, nullptr, ROWPTR, CURSOR, EIDX, rs_din,
                                        b2, nullptr, h2);

    // ---- layer 3 ----
    k_gemm_mma<true><<<dim3(gridM, 1, RR), TPB, GS_TOTAL>>>(h2, W3, rs_dout_ddi, tmp, ND, FO);
    k_gather<false><<<gatherBlk, TPB>>>(tmp, nullptr, ROWPTR, CURSOR, EIDX, rs_din,
                                        b3, nullptr, out);

    (void)in_sizes; (void)n_in; (void)out_size;
}